// round 1
// baseline (speedup 1.0000x reference)
#include <cuda_runtime.h>
#include <cstdint>

#define NN   100000
#define EE   3200000
#define FIN  256
#define HH   512
#define FOUT 256

// ---------------- scratch (device globals: no allocation allowed) ----------
__device__ float g_X1[(size_t)NN * HH];
__device__ float g_X2[(size_t)NN * HH];
__device__ float g_HA[(size_t)NN * HH];
__device__ float g_HB[(size_t)NN * HH];
__device__ float g_B [3 * HH * HH];          // de-interleaved weights [3F, H]
__device__ int   g_rowptr[NN + 1];
__device__ int   g_cnt[NN];                  // counts, then scatter cursors
__device__ int   g_col[EE];
__device__ float g_wgt[EE];

// ---------------- f32x2 packed-FMA helpers (Blackwell) ---------------------
__device__ __forceinline__ uint64_t pack2(float lo, float hi) {
    uint64_t r;
    asm("mov.b64 %0, {%1,%2};" : "=l"(r) : "f"(lo), "f"(hi));
    return r;
}
__device__ __forceinline__ uint64_t ffma2(uint64_t a, uint64_t b, uint64_t c) {
    uint64_t d;
    asm("fma.rn.f32x2 %0, %1, %2, %3;" : "=l"(d) : "l"(a), "l"(b), "l"(c));
    return d;
}
__device__ __forceinline__ float2 unpack2(uint64_t v) {
    float2 f;
    asm("mov.b64 {%0,%1}, %2;" : "=f"(f.x), "=f"(f.y) : "l"(v));
    return f;
}

// ---------------- CSR build -------------------------------------------------
__global__ void zero_cnt_kernel() {
    int i = blockIdx.x * blockDim.x + threadIdx.x;
    if (i < NN) g_cnt[i] = 0;
}

__global__ void count_kernel(const int* __restrict__ rows) {
    int i = blockIdx.x * blockDim.x + threadIdx.x;
    if (i < EE) atomicAdd(&g_cnt[rows[i]], 1);
}

// single-block exclusive scan over g_cnt -> g_rowptr; leaves cursors in g_cnt
__global__ void scan_kernel() {
    __shared__ int s[1024];
    __shared__ int carry;
    int tid = threadIdx.x;
    if (tid == 0) carry = 0;
    __syncthreads();
    for (int base = 0; base < NN; base += 1024) {
        int i = base + tid;
        int v = (i < NN) ? g_cnt[i] : 0;
        s[tid] = v;
        __syncthreads();
        #pragma unroll
        for (int off = 1; off < 1024; off <<= 1) {
            int t = (tid >= off) ? s[tid - off] : 0;
            __syncthreads();
            s[tid] += t;
            __syncthreads();
        }
        int excl = s[tid] - v;
        if (i < NN) {
            int start = carry + excl;
            g_rowptr[i] = start;
            g_cnt[i]    = start;   // cursor for scatter
        }
        __syncthreads();
        if (tid == 1023) carry += s[1023];
        __syncthreads();
    }
    if (tid == 0) g_rowptr[NN] = carry;
}

__global__ void scatter_kernel(const int* __restrict__ rows,
                               const int* __restrict__ cols,
                               const float* __restrict__ w) {
    int i = blockIdx.x * blockDim.x + threadIdx.x;
    if (i < EE) {
        int r = rows[i];
        int p = atomicAdd(&g_cnt[r], 1);
        g_col[p] = cols[i];
        g_wgt[p] = w[i];
    }
}

// ---------------- SpMM: y[r,:] = alpha * sum_e w_e * x[col_e,:] (- sub[r,:]) -
// grid = (NN), blockDim = F/4 (64 or 128), each thread owns 4 features.
__global__ void spmm_kernel(const float* __restrict__ x,
                            const float* __restrict__ sub,
                            float* __restrict__ y,
                            int F, float alpha) {
    __shared__ int   sc[128];
    __shared__ float sw[128];
    int r  = blockIdx.x;
    int t  = threadIdx.x;
    int nt = blockDim.x;
    int beg = g_rowptr[r];
    int end = g_rowptr[r + 1];
    size_t fo = (size_t)t * 4;
    float4 acc = make_float4(0.f, 0.f, 0.f, 0.f);
    for (int base = beg; base < end; base += nt) {
        int m = min(nt, end - base);
        __syncthreads();
        if (t < m) { sc[t] = g_col[base + t]; sw[t] = g_wgt[base + t]; }
        __syncthreads();
        #pragma unroll 4
        for (int j = 0; j < m; j++) {
            float wv = sw[j];
            const float4 xv = *(const float4*)(x + (size_t)sc[j] * F + fo);
            acc.x += wv * xv.x; acc.y += wv * xv.y;
            acc.z += wv * xv.z; acc.w += wv * xv.w;
        }
    }
    float4 o;
    if (sub != nullptr) {
        const float4 s = *(const float4*)(sub + (size_t)r * F + fo);
        o.x = alpha * acc.x - s.x; o.y = alpha * acc.y - s.y;
        o.z = alpha * acc.z - s.z; o.w = alpha * acc.w - s.w;
    } else {
        o.x = alpha * acc.x; o.y = alpha * acc.y;
        o.z = alpha * acc.z; o.w = alpha * acc.w;
    }
    *(float4*)(y + (size_t)r * F + fo) = o;
}

// ---------------- de-interleave weights: B[(k*F+f)*H + o] = W[o, f*3+k] -----
__global__ void split_kernel(const float* __restrict__ W, float* __restrict__ B,
                             int F, int Hdim) {
    int idx = blockIdx.x * blockDim.x + threadIdx.x;
    int tot = 3 * F * Hdim;
    if (idx < tot) {
        int o = idx % Hdim;
        int r = idx / Hdim;
        int k = r / F;
        int f = r % F;
        B[idx] = W[(size_t)o * (3 * F) + f * 3 + k];
    }
}

// ---------------- GEMM: C = relu?( X0@B0 + X1@B1 + X2@B2 + bias ) ----------
// A segments are [N, F] row-major; B is [3F, H] row-major (K-major).
// 128x128 tile, BK=8, 256 threads, 8x8 per thread, f32x2 packed FMA.
template <bool RELU>
__global__ __launch_bounds__(256, 2)
void gemm3_kernel(const float* __restrict__ A0,
                  const float* __restrict__ A1,
                  const float* __restrict__ A2,
                  const float* __restrict__ B,
                  const float* __restrict__ bias,
                  float* __restrict__ C,
                  int n, int F, int Hdim) {
    __shared__ float As[2][8][128];
    __shared__ float Bs[2][8][128];

    const float* Aseg[3] = {A0, A1, A2};

    int tid = threadIdx.x;
    int bm = blockIdx.x * 128;
    int bn = blockIdx.y * 128;

    int aRow = tid >> 1;           // 0..127
    int aCol = (tid & 1) * 4;      // 0 or 4
    int bRow = tid >> 5;           // 0..7
    int bCol = (tid & 31) * 4;     // 0..124

    int gRow = bm + aRow;
    if (gRow >= n) gRow = n - 1;   // clamp; stores are guarded

    int T = (3 * F) / 8;

    // --- load tile 0 ---
    float4 aReg = *(const float4*)(A0 + (size_t)gRow * F + aCol);
    float4 bReg = *(const float4*)(B + (size_t)bRow * Hdim + bn + bCol);
    As[0][aCol + 0][aRow] = aReg.x;
    As[0][aCol + 1][aRow] = aReg.y;
    As[0][aCol + 2][aRow] = aReg.z;
    As[0][aCol + 3][aRow] = aReg.w;
    *(float4*)&Bs[0][bRow][bCol] = bReg;
    __syncthreads();

    uint64_t acc[8][4];
    #pragma unroll
    for (int i = 0; i < 8; i++)
        #pragma unroll
        for (int j = 0; j < 4; j++) acc[i][j] = 0ull;

    int ty = tid >> 4;     // 0..15
    int tx = tid & 15;     // 0..15

    for (int t = 0; t < T; t++) {
        int buf = t & 1;
        bool pf = (t + 1 < T);
        if (pf) {
            int kg  = (t + 1) * 8;
            int seg = kg / F;
            const float* Ap = Aseg[seg];
            int kin = kg - seg * F;
            aReg = *(const float4*)(Ap + (size_t)gRow * F + kin + aCol);
            bReg = *(const float4*)(B + (size_t)(kg + bRow) * Hdim + bn + bCol);
        }
        #pragma unroll
        for (int k = 0; k < 8; k++) {
            float4 a0 = *(const float4*)&As[buf][k][ty * 8];
            float4 a1 = *(const float4*)&As[buf][k][ty * 8 + 4];
            ulonglong2 bb0 = *(const ulonglong2*)&Bs[buf][k][tx * 8];
            ulonglong2 bb1 = *(const ulonglong2*)&Bs[buf][k][tx * 8 + 4];
            uint64_t bv[4] = {bb0.x, bb0.y, bb1.x, bb1.y};
            float av[8] = {a0.x, a0.y, a0.z, a0.w, a1.x, a1.y, a1.z, a1.w};
            #pragma unroll
            for (int i = 0; i < 8; i++) {
                uint64_t ap = pack2(av[i], av[i]);
                #pragma unroll
                for (int j = 0; j < 4; j++)
                    acc[i][j] = ffma2(ap, bv[j], acc[i][j]);
            }
        }
        if (pf) {
            int nb = 1 - buf;
            As[nb][aCol + 0][aRow] = aReg.x;
            As[nb][aCol + 1][aRow] = aReg.y;
            As[nb][aCol + 2][aRow] = aReg.z;
            As[nb][aCol + 3][aRow] = aReg.w;
            *(float4*)&Bs[nb][bRow][bCol] = bReg;
        }
        __syncthreads();
    }

    // --- epilogue ---
    int colBase = bn + tx * 8;
    float bsv[8];
    #pragma unroll
    for (int j = 0; j < 8; j++) bsv[j] = bias[colBase + j];

    #pragma unroll
    for (int i = 0; i < 8; i++) {
        int row = bm + ty * 8 + i;
        if (row < n) {
            float v[8];
            #pragma unroll
            for (int j = 0; j < 4; j++) {
                float2 p = unpack2(acc[i][j]);
                v[2 * j]     = p.x + bsv[2 * j];
                v[2 * j + 1] = p.y + bsv[2 * j + 1];
            }
            if (RELU) {
                #pragma unroll
                for (int j = 0; j < 8; j++) v[j] = fmaxf(v[j], 0.f);
            }
            float4 lo = make_float4(v[0], v[1], v[2], v[3]);
            float4 hi = make_float4(v[4], v[5], v[6], v[7]);
            *(float4*)(C + (size_t)row * Hdim + colBase)     = lo;
            *(float4*)(C + (size_t)row * Hdim + colBase + 4) = hi;
        }
    }
}

// ---------------- host orchestration ---------------------------------------
static void run_layer(const float* in, int F,
                      const float* W, const float* bias, int Hdim,
                      float* X1, float* X2, float* Bm, float* outp, bool relu) {
    spmm_kernel<<<NN, F / 4>>>(in, nullptr, X1, F, 1.f);
    spmm_kernel<<<NN, F / 4>>>(X1, in, X2, F, 2.f);
    int tot = 3 * F * Hdim;
    split_kernel<<<(tot + 255) / 256, 256>>>(W, Bm, F, Hdim);
    dim3 grid((NN + 127) / 128, Hdim / 128);
    if (relu)
        gemm3_kernel<true><<<grid, 256>>>(in, X1, X2, Bm, bias, outp, NN, F, Hdim);
    else
        gemm3_kernel<false><<<grid, 256>>>(in, X1, X2, Bm, bias, outp, NN, F, Hdim);
}

extern "C" void kernel_launch(void* const* d_in, const int* in_sizes, int n_in,
                              void* d_out, int out_size) {
    const float* x    = (const float*)d_in[0];
    const int*   er   = (const int*)d_in[1];
    const int*   ec   = (const int*)d_in[2];
    const float* ew   = (const float*)d_in[3];
    const float* W1   = (const float*)d_in[4];
    const float* b1   = (const float*)d_in[5];
    const float* W2   = (const float*)d_in[6];
    const float* b2   = (const float*)d_in[7];
    const float* W3   = (const float*)d_in[8];
    const float* b3   = (const float*)d_in[9];
    const float* Wout = (const float*)d_in[10];
    const float* bout = (const float*)d_in[11];
    float* out = (float*)d_out;

    float *X1, *X2, *HA, *HB, *Bm;
    cudaGetSymbolAddress((void**)&X1, g_X1);
    cudaGetSymbolAddress((void**)&X2, g_X2);
    cudaGetSymbolAddress((void**)&HA, g_HA);
    cudaGetSymbolAddress((void**)&HB, g_HB);
    cudaGetSymbolAddress((void**)&Bm, g_B);

    // CSR build (per call: deterministic work)
    zero_cnt_kernel<<<(NN + 255) / 256, 256>>>();
    count_kernel<<<(EE + 255) / 256, 256>>>(er);
    scan_kernel<<<1, 1024>>>();
    scatter_kernel<<<(EE + 255) / 256, 256>>>(er, ec, ew);

    run_layer(x,  FIN, W1,   b1,   HH,   X1, X2, Bm, HA,  true);
    run_layer(HA, HH,  W2,   b2,   HH,   X1, X2, Bm, HB,  true);
    run_layer(HB, HH,  W3,   b3,   HH,   X1, X2, Bm, HA,  true);
    run_layer(HA, HH,  Wout, bout, FOUT, X1, X2, Bm, out, false);
}

// round 3
// speedup vs baseline: 2.4753x; 2.4753x over previous
#include <cuda_runtime.h>
#include <cstdint>

#define NN   100000
#define EE   3200000
#define FIN  256
#define HH   512
#define FOUT 256

#define BM 128
#define BN 128
#define BK 32
#define STAGES 3
#define STAGE_BYTES 32768
#define SMEM_BYTES (STAGES * STAGE_BYTES)

// swizzle: bits[6:4] ^= bits[9:7]  (SW128 pattern for 128B rows)
#define SW(o) ((o) ^ (((o) >> 3) & 0x70))

// ---------------- scratch (device globals: no allocation allowed) ----------
__device__ float g_X1[(size_t)NN * HH];
__device__ float g_X2[(size_t)NN * HH];
__device__ float g_HA[(size_t)NN * HH];
__device__ float g_HB[(size_t)NN * HH];
__device__ float g_X0r[(size_t)NN * FIN];     // tf32-rounded copy of x
__device__ float g_B [3 * HH * HH];           // de-interleaved weights [H, 3F]
__device__ int   g_rowptr[NN + 1];
__device__ int   g_cnt[NN];
__device__ int   g_col[EE];
__device__ float g_wgt[EE];

// ---------------- helpers ---------------------------------------------------
__device__ __forceinline__ float tf32r(float x) {
    uint32_t r;
    asm("cvt.rna.tf32.f32 %0, %1;" : "=r"(r) : "f"(x));
    return __uint_as_float(r);
}

__device__ __forceinline__ uint32_t smem_u32(const void* p) {
    uint32_t a;
    asm("{ .reg .u64 t; cvta.to.shared.u64 t, %1; cvt.u32.u64 %0, t; }" : "=r"(a) : "l"(p));
    return a;
}

template <int N>
__device__ __forceinline__ void cp_wait_group() {
    asm volatile("cp.async.wait_group %0;" :: "n"(N) : "memory");
}

__device__ __forceinline__ void cp16(uint32_t dst, const void* src) {
    asm volatile("cp.async.cg.shared.global [%0], [%1], 16;" :: "r"(dst), "l"(src));
}

__device__ __forceinline__ void ldsm4(uint32_t* r, uint32_t addr) {
    asm volatile("ldmatrix.sync.aligned.m8n8.x4.shared.b16 {%0,%1,%2,%3}, [%4];"
                 : "=r"(r[0]), "=r"(r[1]), "=r"(r[2]), "=r"(r[3]) : "r"(addr));
}

__device__ __forceinline__ void mma_tf32(float* c, const uint32_t* a,
                                         uint32_t b0, uint32_t b1) {
    asm volatile(
        "mma.sync.aligned.m16n8k8.row.col.f32.tf32.tf32.f32 "
        "{%0,%1,%2,%3}, {%4,%5,%6,%7}, {%8,%9}, {%0,%1,%2,%3};"
        : "+f"(c[0]), "+f"(c[1]), "+f"(c[2]), "+f"(c[3])
        : "r"(a[0]), "r"(a[1]), "r"(a[2]), "r"(a[3]), "r"(b0), "r"(b1));
}

// ---------------- CSR build -------------------------------------------------
__global__ void zero_cnt_kernel() {
    int i = blockIdx.x * blockDim.x + threadIdx.x;
    if (i < NN) g_cnt[i] = 0;
}

__global__ void count_kernel(const int* __restrict__ rows) {
    int i = blockIdx.x * blockDim.x + threadIdx.x;
    if (i < EE) atomicAdd(&g_cnt[rows[i]], 1);
}

__global__ void scan_kernel() {
    __shared__ int s[1024];
    __shared__ int carry;
    int tid = threadIdx.x;
    if (tid == 0) carry = 0;
    __syncthreads();
    for (int base = 0; base < NN; base += 1024) {
        int i = base + tid;
        int v = (i < NN) ? g_cnt[i] : 0;
        s[tid] = v;
        __syncthreads();
        #pragma unroll
        for (int off = 1; off < 1024; off <<= 1) {
            int t = (tid >= off) ? s[tid - off] : 0;
            __syncthreads();
            s[tid] += t;
            __syncthreads();
        }
        int excl = s[tid] - v;
        if (i < NN) {
            int start = carry + excl;
            g_rowptr[i] = start;
            g_cnt[i]    = start;
        }
        __syncthreads();
        if (tid == 1023) carry += s[1023];
        __syncthreads();
    }
    if (tid == 0) g_rowptr[NN] = carry;
}

__global__ void scatter_kernel(const int* __restrict__ rows,
                               const int* __restrict__ cols,
                               const float* __restrict__ w) {
    int i = blockIdx.x * blockDim.x + threadIdx.x;
    if (i < EE) {
        int r = rows[i];
        int p = atomicAdd(&g_cnt[r], 1);
        g_col[p] = cols[i];
        g_wgt[p] = w[i];
    }
}

// ---------------- SpMM (256-feature chunk, 64 threads/block) ----------------
__global__ void spmm_kernel(const float* __restrict__ x,
                            const float* __restrict__ sub,
                            float* __restrict__ y,
                            int stride, float alpha) {
    __shared__ int   sc[64];
    __shared__ float sw[64];
    int r = blockIdx.x;
    int t = threadIdx.x;
    int beg = g_rowptr[r];
    int end = g_rowptr[r + 1];
    int fo = t * 4;
    float4 acc = make_float4(0.f, 0.f, 0.f, 0.f);
    for (int base = beg; base < end; base += 64) {
        int m = min(64, end - base);
        __syncthreads();
        if (t < m) { sc[t] = g_col[base + t]; sw[t] = g_wgt[base + t]; }
        __syncthreads();
        #pragma unroll 4
        for (int j = 0; j < m; j++) {
            float wv = sw[j];
            const float4 xv = *(const float4*)(x + (size_t)sc[j] * stride + fo);
            acc.x += wv * xv.x; acc.y += wv * xv.y;
            acc.z += wv * xv.z; acc.w += wv * xv.w;
        }
    }
    float4 o;
    if (sub != nullptr) {
        const float4 s = *(const float4*)(sub + (size_t)r * stride + fo);
        o.x = tf32r(alpha * acc.x - s.x); o.y = tf32r(alpha * acc.y - s.y);
        o.z = tf32r(alpha * acc.z - s.z); o.w = tf32r(alpha * acc.w - s.w);
    } else {
        o.x = tf32r(alpha * acc.x); o.y = tf32r(alpha * acc.y);
        o.z = tf32r(alpha * acc.z); o.w = tf32r(alpha * acc.w);
    }
    *(float4*)(y + (size_t)r * stride + fo) = o;
}

// ---------------- de-interleave weights: Bt[o, seg*F+f] = W[o, f*3+seg] -----
__global__ void split_kernel(const float* __restrict__ W, float* __restrict__ B,
                             int F, int Hdim) {
    int idx = blockIdx.x * blockDim.x + threadIdx.x;
    int tot = 3 * F * Hdim;
    if (idx < tot) {
        int kk = idx % (3 * F);
        int o  = idx / (3 * F);
        int seg = kk / F;
        int f   = kk % F;
        B[idx] = tf32r(W[(size_t)o * (3 * F) + f * 3 + seg]);
    }
}

__global__ void round_kernel(const float* __restrict__ in, float* __restrict__ out, int n) {
    int i = blockIdx.x * blockDim.x + threadIdx.x;
    if (i < n) out[i] = tf32r(in[i]);
}

// ---------------- mma.sync tf32 GEMM ----------------------------------------
// C[n, Hdim] = relu?( [A0|A1|A2] @ Bt^T + bias ), Bt is [Hdim, 3F] K-major.
// BM=128, BN=128, BK=32, 256 threads (8 warps, 2m x 4n), warp tile 64x32.
__device__ __forceinline__ void load_tile(uint32_t sb, int s, int kt,
                                          const float* __restrict__ A0,
                                          const float* __restrict__ A1,
                                          const float* __restrict__ A2,
                                          const float* __restrict__ Bt,
                                          int n, int F, int Ktot,
                                          int bm, int bn, int tid) {
    int kg  = kt * BK;
    int seg = kg / F;
    const float* Ap = (seg == 0) ? A0 : ((seg == 1) ? A1 : A2);
    int kin = kg - seg * F;
    uint32_t abase = sb + s * STAGE_BYTES;
    uint32_t bbase = abase + 16384;
    #pragma unroll
    for (int i = 0; i < 4; i++) {
        int lin = i * 256 + tid;
        int row = lin >> 3;
        int c4  = lin & 7;
        int gr = bm + row;
        if (gr >= n) gr = n - 1;
        uint32_t off = row * 128 + c4 * 16;
        cp16(abase + SW(off), Ap + (size_t)gr * F + kin + c4 * 4);
    }
    #pragma unroll
    for (int i = 0; i < 4; i++) {
        int lin = i * 256 + tid;
        int row = lin >> 3;
        int c4  = lin & 7;
        uint32_t off = row * 128 + c4 * 16;
        cp16(bbase + SW(off), Bt + (size_t)(bn + row) * Ktot + kg + c4 * 4);
    }
}

template <bool RELU>
__global__ __launch_bounds__(256, 2)
void gemm_mma_kernel(const float* __restrict__ A0,
                     const float* __restrict__ A1,
                     const float* __restrict__ A2,
                     const float* __restrict__ Bt,
                     const float* __restrict__ bias,
                     float* __restrict__ C,
                     int n, int F, int Hdim) {
    extern __shared__ char smem[];
    uint32_t sb = smem_u32(smem);
    int tid  = threadIdx.x;
    int lane = tid & 31;
    int wid  = tid >> 5;
    int wm = wid & 1;        // 0..1 -> 64 rows each
    int wn = wid >> 1;       // 0..3 -> 32 cols each
    int bn = blockIdx.x * BN;
    int bm = blockIdx.y * BM;
    int Ktot = 3 * F;
    int T = Ktot / BK;

    float c[4][4][4];
    #pragma unroll
    for (int mi = 0; mi < 4; mi++)
        #pragma unroll
        for (int j = 0; j < 4; j++)
            #pragma unroll
            for (int e = 0; e < 4; e++) c[mi][j][e] = 0.f;

    // prologue: stages 0..STAGES-2
    #pragma unroll
    for (int p = 0; p < STAGES - 1; p++) {
        load_tile(sb, p, p, A0, A1, A2, Bt, n, F, Ktot, bm, bn, tid);
        asm volatile("cp.async.commit_group;" ::: "memory");
    }

    // ldmatrix addressing (same row pattern for A and B)
    int lrow = (lane & 7) + (lane & 8);      // row within 16-row tile
    int lcol = (lane >> 4) << 4;             // 0 or 16 bytes

    for (int t = 0; t < T; t++) {
        cp_wait_group<STAGES - 2>();
        __syncthreads();
        int pt = t + STAGES - 1;
        if (pt < T)
            load_tile(sb, pt % STAGES, pt, A0, A1, A2, Bt, n, F, Ktot, bm, bn, tid);
        asm volatile("cp.async.commit_group;" ::: "memory");

        uint32_t abase = sb + (t % STAGES) * STAGE_BYTES;
        uint32_t bbase = abase + 16384;

        #pragma unroll
        for (int ks = 0; ks < 4; ks++) {
            int colb = ks * 32 + lcol;
            uint32_t a[4][4];
            #pragma unroll
            for (int mi = 0; mi < 4; mi++) {
                uint32_t off = (uint32_t)((wm * 64 + mi * 16 + lrow) * 128 + colb);
                ldsm4(a[mi], abase + SW(off));
            }
            uint32_t b[2][4];
            #pragma unroll
            for (int nj = 0; nj < 2; nj++) {
                uint32_t off = (uint32_t)((wn * 32 + nj * 16 + lrow) * 128 + colb);
                ldsm4(b[nj], bbase + SW(off));
            }
            #pragma unroll
            for (int mi = 0; mi < 4; mi++)
                #pragma unroll
                for (int j = 0; j < 4; j++)
                    mma_tf32(c[mi][j], a[mi], b[j >> 1][j & 1], b[j >> 1][2 + (j & 1)]);
        }
    }

    // epilogue
    #pragma unroll
    for (int mi = 0; mi < 4; mi++) {
        int r0 = bm + wm * 64 + mi * 16 + (lane >> 2);
        #pragma unroll
        for (int j = 0; j < 4; j++) {
            int col = bn + wn * 32 + j * 8 + (lane & 3) * 2;
            float b0 = bias[col], b1 = bias[col + 1];
            if (r0 < n) {
                float v0 = c[mi][j][0] + b0;
                float v1 = c[mi][j][1] + b1;
                if (RELU) { v0 = tf32r(fmaxf(v0, 0.f)); v1 = tf32r(fmaxf(v1, 0.f)); }
                *(float2*)(C + (size_t)r0 * Hdim + col) = make_float2(v0, v1);
            }
            if (r0 + 8 < n) {
                float v2 = c[mi][j][2] + b0;
                float v3 = c[mi][j][3] + b1;
                if (RELU) { v2 = tf32r(fmaxf(v2, 0.f)); v3 = tf32r(fmaxf(v3, 0.f)); }
                *(float2*)(C + (size_t)(r0 + 8) * Hdim + col) = make_float2(v2, v3);
            }
        }
    }
}

// ---------------- host orchestration ---------------------------------------
static void run_layer(const float* in_spmm, const float* in_gemm, int F,
                      const float* W, const float* bias, int Hdim,
                      float* X1, float* X2, float* Bm, float* outp, bool relu) {
    for (int c = 0; c < F / 256; c++) {
        int f0 = c * 256;
        spmm_kernel<<<NN, 64>>>(in_spmm + f0, nullptr, X1 + f0, F, 1.f);
        spmm_kernel<<<NN, 64>>>(X1 + f0, in_spmm + f0, X2 + f0, F, 2.f);
    }
    int tot = 3 * F * Hdim;
    split_kernel<<<(tot + 255) / 256, 256>>>(W, Bm, F, Hdim);
    dim3 grid(Hdim / BN, (NN + BM - 1) / BM);
    if (relu)
        gemm_mma_kernel<true><<<grid, 256, SMEM_BYTES>>>(in_gemm, X1, X2, Bm, bias, outp, NN, F, Hdim);
    else
        gemm_mma_kernel<false><<<grid, 256, SMEM_BYTES>>>(in_gemm, X1, X2, Bm, bias, outp, NN, F, Hdim);
}

extern "C" void kernel_launch(void* const* d_in, const int* in_sizes, int n_in,
                              void* d_out, int out_size) {
    const float* x    = (const float*)d_in[0];
    const int*   er   = (const int*)d_in[1];
    const int*   ec   = (const int*)d_in[2];
    const float* ew   = (const float*)d_in[3];
    const float* W1   = (const float*)d_in[4];
    const float* b1   = (const float*)d_in[5];
    const float* W2   = (const float*)d_in[6];
    const float* b2   = (const float*)d_in[7];
    const float* W3   = (const float*)d_in[8];
    const float* b3   = (const float*)d_in[9];
    const float* Wout = (const float*)d_in[10];
    const float* bout = (const float*)d_in[11];
    float* out = (float*)d_out;

    float *X1, *X2, *HA, *HB, *Bm, *X0r;
    cudaGetSymbolAddress((void**)&X1,  g_X1);
    cudaGetSymbolAddress((void**)&X2,  g_X2);
    cudaGetSymbolAddress((void**)&HA,  g_HA);
    cudaGetSymbolAddress((void**)&HB,  g_HB);
    cudaGetSymbolAddress((void**)&Bm,  g_B);
    cudaGetSymbolAddress((void**)&X0r, g_X0r);

    cudaFuncSetAttribute(gemm_mma_kernel<true>,  cudaFuncAttributeMaxDynamicSharedMemorySize, SMEM_BYTES);
    cudaFuncSetAttribute(gemm_mma_kernel<false>, cudaFuncAttributeMaxDynamicSharedMemorySize, SMEM_BYTES);

    // CSR build
    zero_cnt_kernel<<<(NN + 255) / 256, 256>>>();
    count_kernel<<<(EE + 255) / 256, 256>>>(er);
    scan_kernel<<<1, 1024>>>();
    scatter_kernel<<<(EE + 255) / 256, 256>>>(er, ec, ew);

    // tf32-rounded copy of x (GEMM A0 operand for layer 1)
    round_kernel<<<(NN * FIN + 255) / 256, 256>>>(x, X0r, NN * FIN);

    run_layer(x,  X0r, FIN, W1,   b1,   HH,   X1, X2, Bm, HA,  true);
    run_layer(HA, HA,  HH,  W2,   b2,   HH,   X1, X2, Bm, HB,  true);
    run_layer(HB, HB,  HH,  W3,   b3,   HH,   X1, X2, Bm, HA,  true);
    run_layer(HA, HA,  HH,  Wout, bout, FOUT, X1, X2, Bm, out, false);
}

// round 5
// speedup vs baseline: 4.4976x; 1.8170x over previous
#include <cuda_runtime.h>
#include <cuda_fp16.h>
#include <cstdint>

#define NN   100000
#define EE   3200000
#define FIN  256
#define HH   512
#define FOUT 256

#define BM 128
#define BN 128
#define BKH 64               /* K halves per stage (128B rows) */
#define STAGES 3
#define STAGE_BYTES 32768    /* 16KB A + 16KB B */
#define SMEM_BYTES (STAGES * STAGE_BYTES)

#define ACT_SCALE   0.00390625f   /* 2^-8 */
#define ACT_UNSCALE 256.0f

// swizzle: bits[6:4] ^= bits[9:7]  (SW128 pattern for 128B rows)
#define SW(o) ((o) ^ (((o) >> 3) & 0x70))

// ---------------- scratch (device globals: no allocation allowed) ----------
__device__ __half g_X0h[(size_t)NN * FIN];
__device__ __half g_X1[(size_t)NN * HH];
__device__ __half g_X2[(size_t)NN * HH];
__device__ __half g_HA[(size_t)NN * HH];
__device__ __half g_HB[(size_t)NN * HH];
__device__ __half g_B [3 * HH * HH];          // de-interleaved weights [H, 3F]
__device__ int    g_rowptr[NN + 1];
__device__ int    g_cnt[NN];
__device__ int    g_col[EE];
__device__ float  g_wgt[EE];

// ---------------- helpers ---------------------------------------------------
__device__ __forceinline__ uint32_t smem_u32(const void* p) {
    uint32_t a;
    asm("{ .reg .u64 t; cvta.to.shared.u64 t, %1; cvt.u32.u64 %0, t; }" : "=r"(a) : "l"(p));
    return a;
}

template <int N>
__device__ __forceinline__ void cp_wait_group() {
    asm volatile("cp.async.wait_group %0;" :: "n"(N) : "memory");
}

__device__ __forceinline__ void cp16(uint32_t dst, const void* src) {
    asm volatile("cp.async.cg.shared.global [%0], [%1], 16;" :: "r"(dst), "l"(src));
}

__device__ __forceinline__ void ldsm4(uint32_t* r, uint32_t addr) {
    asm volatile("ldmatrix.sync.aligned.m8n8.x4.shared.b16 {%0,%1,%2,%3}, [%4];"
                 : "=r"(r[0]), "=r"(r[1]), "=r"(r[2]), "=r"(r[3]) : "r"(addr));
}

__device__ __forceinline__ void mma_f16(float* c, const uint32_t* a,
                                        uint32_t b0, uint32_t b1) {
    asm volatile(
        "mma.sync.aligned.m16n8k16.row.col.f32.f16.f16.f32 "
        "{%0,%1,%2,%3}, {%4,%5,%6,%7}, {%8,%9}, {%0,%1,%2,%3};"
        : "+f"(c[0]), "+f"(c[1]), "+f"(c[2]), "+f"(c[3])
        : "r"(a[0]), "r"(a[1]), "r"(a[2]), "r"(a[3]), "r"(b0), "r"(b1));
}

// ---------------- CSR build -------------------------------------------------
__global__ void zero_cnt_kernel() {
    int i = blockIdx.x * blockDim.x + threadIdx.x;
    if (i < NN) g_cnt[i] = 0;
}

__global__ void count_kernel(const int* __restrict__ rows) {
    int i = blockIdx.x * blockDim.x + threadIdx.x;
    if (i < EE) atomicAdd(&g_cnt[rows[i]], 1);
}

__global__ void scan_kernel() {
    __shared__ int s[1024];
    __shared__ int carry;
    int tid = threadIdx.x;
    if (tid == 0) carry = 0;
    __syncthreads();
    for (int base = 0; base < NN; base += 1024) {
        int i = base + tid;
        int v = (i < NN) ? g_cnt[i] : 0;
        s[tid] = v;
        __syncthreads();
        #pragma unroll
        for (int off = 1; off < 1024; off <<= 1) {
            int t = (tid >= off) ? s[tid - off] : 0;
            __syncthreads();
            s[tid] += t;
            __syncthreads();
        }
        int excl = s[tid] - v;
        if (i < NN) {
            int start = carry + excl;
            g_rowptr[i] = start;
            g_cnt[i]    = start;
        }
        __syncthreads();
        if (tid == 1023) carry += s[1023];
        __syncthreads();
    }
    if (tid == 0) g_rowptr[NN] = carry;
}

__global__ void scatter_kernel(const int* __restrict__ rows,
                               const int* __restrict__ cols,
                               const float* __restrict__ w) {
    int i = blockIdx.x * blockDim.x + threadIdx.x;
    if (i < EE) {
        int r = rows[i];
        int p = atomicAdd(&g_cnt[r], 1);
        g_col[p] = cols[i];
        g_wgt[p] = w[i];
    }
}

// ---------------- SpMM (fp16 data, fp32 accumulate, 256-feature chunk) ------
// grid = NN rows, 64 threads; each thread owns 4 halves (uint2 gather).
__global__ void spmm_kernel(const __half* __restrict__ x,
                            const __half* __restrict__ sub,
                            __half* __restrict__ y,
                            int stride, float alpha) {
    __shared__ int   sc[64];
    __shared__ float sw[64];
    int r = blockIdx.x;
    int t = threadIdx.x;
    int beg = g_rowptr[r];
    int end = g_rowptr[r + 1];
    int fo = t * 4;
    float a0 = 0.f, a1 = 0.f, a2 = 0.f, a3 = 0.f;
    for (int base = beg; base < end; base += 64) {
        int m = min(64, end - base);
        __syncthreads();
        if (t < m) { sc[t] = g_col[base + t]; sw[t] = g_wgt[base + t]; }
        __syncthreads();
        #pragma unroll 4
        for (int j = 0; j < m; j++) {
            float wv = sw[j];
            uint2 v = *(const uint2*)(x + (size_t)sc[j] * stride + fo);
            float2 f0 = __half22float2(*(__half2*)&v.x);
            float2 f1 = __half22float2(*(__half2*)&v.y);
            a0 += wv * f0.x; a1 += wv * f0.y;
            a2 += wv * f1.x; a3 += wv * f1.y;
        }
    }
    float o0, o1, o2, o3;
    if (sub != nullptr) {
        uint2 v = *(const uint2*)(sub + (size_t)r * stride + fo);
        float2 s0 = __half22float2(*(__half2*)&v.x);
        float2 s1 = __half22float2(*(__half2*)&v.y);
        o0 = alpha * a0 - s0.x; o1 = alpha * a1 - s0.y;
        o2 = alpha * a2 - s1.x; o3 = alpha * a3 - s1.y;
    } else {
        o0 = alpha * a0; o1 = alpha * a1; o2 = alpha * a2; o3 = alpha * a3;
    }
    uint2 ov;
    *(__half2*)&ov.x = __floats2half2_rn(o0, o1);
    *(__half2*)&ov.y = __floats2half2_rn(o2, o3);
    *(uint2*)(y + (size_t)r * stride + fo) = ov;
}

// ---------------- de-interleave weights: Bt[o, seg*F+f] = W[o, f*3+seg] -----
__global__ void split_kernel(const float* __restrict__ W, __half* __restrict__ B,
                             int F, int Hdim) {
    int idx = blockIdx.x * blockDim.x + threadIdx.x;
    int tot = 3 * F * Hdim;
    if (idx < tot) {
        int kk = idx % (3 * F);
        int o  = idx / (3 * F);
        int seg = kk / F;
        int f   = kk % F;
        B[idx] = __float2half_rn(W[(size_t)o * (3 * F) + f * 3 + seg]);
    }
}

// x -> fp16 with activation pre-scale (exact power of two)
__global__ void round_kernel(const float* __restrict__ in, __half* __restrict__ out, int n) {
    int i = blockIdx.x * blockDim.x + threadIdx.x;
    if (i < n) out[i] = __float2half_rn(in[i] * ACT_SCALE);
}

// ---------------- mma.sync fp16 GEMM -----------------------------------------
// C[n, Hdim] = relu?( [A0|A1|A2] @ Bt^T * out_scale + bias * bias_scale )
// Bt is [Hdim, 3F] K-major fp16. BM=128, BN=128, BK=64 halves, 256 threads.
__device__ __forceinline__ void load_tile(uint32_t sb, int s, int kt,
                                          const __half* __restrict__ A0,
                                          const __half* __restrict__ A1,
                                          const __half* __restrict__ A2,
                                          const __half* __restrict__ Bt,
                                          int n, int F, int Ktot,
                                          int bm, int bn, int tid) {
    int kg  = kt * BKH;
    int seg = kg / F;
    const __half* Ap = (seg == 0) ? A0 : ((seg == 1) ? A1 : A2);
    int kin = kg - seg * F;
    uint32_t abase = sb + s * STAGE_BYTES;
    uint32_t bbase = abase + 16384;
    #pragma unroll
    for (int i = 0; i < 4; i++) {
        int lin = i * 256 + tid;
        int row = lin >> 3;
        int c16 = lin & 7;
        int gr = bm + row;
        if (gr >= n) gr = n - 1;
        uint32_t off = row * 128 + c16 * 16;
        cp16(abase + SW(off), Ap + (size_t)gr * F + kin + c16 * 8);
    }
    #pragma unroll
    for (int i = 0; i < 4; i++) {
        int lin = i * 256 + tid;
        int row = lin >> 3;
        int c16 = lin & 7;
        uint32_t off = row * 128 + c16 * 16;
        cp16(bbase + SW(off), Bt + (size_t)(bn + row) * Ktot + kg + c16 * 8);
    }
}

template <bool RELU, bool HALF_OUT>
__global__ __launch_bounds__(256, 2)
void gemm_mma_kernel(const __half* __restrict__ A0,
                     const __half* __restrict__ A1,
                     const __half* __restrict__ A2,
                     const __half* __restrict__ Bt,
                     const float* __restrict__ bias,
                     void* __restrict__ Cv,
                     int n, int F, int Hdim,
                     float out_scale, float bias_scale) {
    extern __shared__ char smem[];
    uint32_t sb = smem_u32(smem);
    int tid  = threadIdx.x;
    int lane = tid & 31;
    int wid  = tid >> 5;
    int wm = wid & 1;
    int wn = wid >> 1;
    int bn = blockIdx.x * BN;
    int bm = blockIdx.y * BM;
    int Ktot = 3 * F;
    int T = Ktot / BKH;

    float c[4][4][4];
    #pragma unroll
    for (int mi = 0; mi < 4; mi++)
        #pragma unroll
        for (int j = 0; j < 4; j++)
            #pragma unroll
            for (int e = 0; e < 4; e++) c[mi][j][e] = 0.f;

    #pragma unroll
    for (int p = 0; p < STAGES - 1; p++) {
        load_tile(sb, p, p, A0, A1, A2, Bt, n, F, Ktot, bm, bn, tid);
        asm volatile("cp.async.commit_group;" ::: "memory");
    }

    int lrow16 = lane & 15;
    int lhalf  = (lane >> 4) << 4;

    for (int t = 0; t < T; t++) {
        cp_wait_group<STAGES - 2>();
        __syncthreads();
        int pt = t + STAGES - 1;
        if (pt < T)
            load_tile(sb, pt % STAGES, pt, A0, A1, A2, Bt, n, F, Ktot, bm, bn, tid);
        asm volatile("cp.async.commit_group;" ::: "memory");

        uint32_t abase = sb + (t % STAGES) * STAGE_BYTES;
        uint32_t bbase = abase + 16384;

        #pragma unroll
        for (int ks = 0; ks < 4; ks++) {
            int colb = ks * 32 + lhalf;
            uint32_t a[4][4];
            #pragma unroll
            for (int mi = 0; mi < 4; mi++) {
                uint32_t off = (uint32_t)((wm * 64 + mi * 16 + lrow16) * 128 + colb);
                ldsm4(a[mi], abase + SW(off));
            }
            uint32_t b[2][4];
            #pragma unroll
            for (int p = 0; p < 2; p++) {
                uint32_t off = (uint32_t)((wn * 32 + p * 16 + lrow16) * 128 + colb);
                ldsm4(b[p], bbase + SW(off));
            }
            #pragma unroll
            for (int mi = 0; mi < 4; mi++)
                #pragma unroll
                for (int j = 0; j < 4; j++)
                    mma_f16(c[mi][j], a[mi], b[j >> 1][j & 1], b[j >> 1][2 + (j & 1)]);
        }
    }

    // epilogue
    #pragma unroll
    for (int mi = 0; mi < 4; mi++) {
        int r0 = bm + wm * 64 + mi * 16 + (lane >> 2);
        #pragma unroll
        for (int j = 0; j < 4; j++) {
            int col = bn + wn * 32 + j * 8 + (lane & 3) * 2;
            float bb0 = bias[col] * bias_scale;
            float bb1 = bias[col + 1] * bias_scale;
            #pragma unroll
            for (int h = 0; h < 2; h++) {
                int r = r0 + h * 8;
                if (r < n) {
                    float v0 = c[mi][j][2 * h]     * out_scale + bb0;
                    float v1 = c[mi][j][2 * h + 1] * out_scale + bb1;
                    if (RELU) { v0 = fmaxf(v0, 0.f); v1 = fmaxf(v1, 0.f); }
                    if (HALF_OUT) {
                        __half2* Ch = (__half2*)((__half*)Cv + (size_t)r * Hdim + col);
                        *Ch = __floats2half2_rn(v0, v1);
                    } else {
                        *(float2*)((float*)Cv + (size_t)r * Hdim + col) = make_float2(v0, v1);
                    }
                }
            }
        }
    }
}

// ---------------- host orchestration ---------------------------------------
static void run_layer(const __half* in, int F,
                      const float* W, const float* bias, int Hdim,
                      __half* X1, __half* X2, __half* Bm,
                      void* outp, bool hidden) {
    for (int c = 0; c < F / 256; c++) {
        int f0 = c * 256;
        spmm_kernel<<<NN, 64>>>(in + f0, nullptr, X1 + f0, F, 1.f);
        spmm_kernel<<<NN, 64>>>(X1 + f0, in + f0, X2 + f0, F, 2.f);
    }
    int tot = 3 * F * Hdim;
    split_kernel<<<(tot + 255) / 256, 256>>>(W, Bm, F, Hdim);
    dim3 grid(Hdim / BN, (NN + BM - 1) / BM);
    if (hidden)
        gemm_mma_kernel<true, true><<<grid, 256, SMEM_BYTES>>>(
            in, X1, X2, Bm, bias, outp, NN, F, Hdim, 1.f, ACT_SCALE);
    else
        gemm_mma_kernel<false, false><<<grid, 256, SMEM_BYTES>>>(
            in, X1, X2, Bm, bias, outp, NN, F, Hdim, ACT_UNSCALE, 1.f);
}

extern "C" void kernel_launch(void* const* d_in, const int* in_sizes, int n_in,
                              void* d_out, int out_size) {
    const float* x    = (const float*)d_in[0];
    const int*   er   = (const int*)d_in[1];
    const int*   ec   = (const int*)d_in[2];
    const float* ew   = (const float*)d_in[3];
    const float* W1   = (const float*)d_in[4];
    const float* b1   = (const float*)d_in[5];
    const float* W2   = (const float*)d_in[6];
    const float* b2   = (const float*)d_in[7];
    const float* W3   = (const float*)d_in[8];
    const float* b3   = (const float*)d_in[9];
    const float* Wout = (const float*)d_in[10];
    const float* bout = (const float*)d_in[11];
    float* out = (float*)d_out;

    __half *X0h, *X1, *X2, *HA, *HB, *Bm;
    cudaGetSymbolAddress((void**)&X0h, g_X0h);
    cudaGetSymbolAddress((void**)&X1,  g_X1);
    cudaGetSymbolAddress((void**)&X2,  g_X2);
    cudaGetSymbolAddress((void**)&HA,  g_HA);
    cudaGetSymbolAddress((void**)&HB,  g_HB);
    cudaGetSymbolAddress((void**)&Bm,  g_B);

    cudaFuncSetAttribute(gemm_mma_kernel<true, true>,
                         cudaFuncAttributeMaxDynamicSharedMemorySize, SMEM_BYTES);
    cudaFuncSetAttribute(gemm_mma_kernel<false, false>,
                         cudaFuncAttributeMaxDynamicSharedMemorySize, SMEM_BYTES);

    // CSR build
    zero_cnt_kernel<<<(NN + 255) / 256, 256>>>();
    count_kernel<<<(EE + 255) / 256, 256>>>(er);
    scan_kernel<<<1, 1024>>>();
    scatter_kernel<<<(EE + 255) / 256, 256>>>(er, ec, ew);

    // fp16 copy of x, pre-scaled by 2^-8
    round_kernel<<<(NN * FIN + 255) / 256, 256>>>(x, X0h, NN * FIN);

    run_layer(X0h, FIN, W1,   b1,   HH,   X1, X2, Bm, HA,  true);
    run_layer(HA,  HH,  W2,   b2,   HH,   X1, X2, Bm, HB,  true);
    run_layer(HB,  HH,  W3,   b3,   HH,   X1, X2, Bm, HA,  true);
    run_layer(HA,  HH,  Wout, bout, FOUT, X1, X2, Bm, out, false);
}